// round 5
// baseline (speedup 1.0000x reference)
#include <cuda_runtime.h>

// QuantizedCodebook (VQ-VAE): N=131072 rows, D=64, K=512.
// out layout (confirmed): [loss(1) | quantize(N*D) | indices(N)] fp32.
// 16 warps/SM; thread tile = 4 rows x 16 codes (8 f32x2 code-pairs).

#define KCODES 512
#define DDIM   64
#define TPB    512
#define TROWS  4            // rows per warp
#define TPAIRS 8            // code-pairs per lane (pair = lane + 32m)
#define TILE_R 64           // rows per block tile (16 warps * 4 rows)
#define MAXBLK 512

typedef unsigned long long ull;

__device__ double   g_partials[MAXBLK];
__device__ unsigned g_done;   // zero-init; last block resets each run

__device__ __forceinline__ ull f32x2_dup(float v) {
    ull r; asm("mov.b64 %0, {%1, %1};" : "=l"(r) : "f"(v)); return r;
}
__device__ __forceinline__ ull ffma2(ull a, ull b, ull c) {
    ull d; asm("fma.rn.f32x2 %0, %1, %2, %3;" : "=l"(d) : "l"(a), "l"(b), "l"(c));
    return d;
}
__device__ __forceinline__ float2 as_float2(ull a) {
    float2 f; asm("mov.b64 {%0, %1}, %2;" : "=f"(f.x), "=f"(f.y) : "l"(a));
    return f;
}

__global__ void __launch_bounds__(TPB, 1)
vq_kernel(const float* __restrict__ x, const float* __restrict__ cb,
          float* __restrict__ out, int nrows)
{
    // smem: cbTf[64][512] dim-major (128KB) | xd[64][64] dup rows (32KB) | scq[512]
    extern __shared__ unsigned char smem_raw[];
    float* cbTf = (float*)smem_raw;                          // [i*512 + c]
    ull*   xd   = (ull*)(smem_raw + KCODES * DDIM * 4);      // [r*64 + i] = {x,x}
    float* scq  = (float*)(smem_raw + KCODES * DDIM * 4 + TILE_R * DDIM * 8);

    float* out_q   = out + 1;
    float* out_idx = out + 1 + (size_t)nrows * DDIM;

    const int tid  = threadIdx.x;
    const int w    = tid >> 5;
    const int lane = tid & 31;

    // ---- One-time: codebook -> smem dim-major transpose; ||c||^2 ----
    for (int idx = tid; idx < KCODES * DDIM; idx += TPB) {
        int i = idx >> 9;
        int c = idx & (KCODES - 1);
        cbTf[idx] = cb[c * DDIM + i];
    }
    for (int c = tid; c < KCODES; c += TPB) {
        const float* cr = cb + c * DDIM;
        float s = 0.f;
        #pragma unroll
        for (int i = 0; i < DDIM; i++) s = fmaf(cr[i], cr[i], s);
        scq[c] = s;
    }
    __syncthreads();

    const ull*    cbp  = (const ull*)cbTf;      // [i*256 + pair]
    const float2* scq2 = (const float2*)scq;    // [pair]

    const int ntiles = nrows / TILE_R;          // 2048
    float lsum = 0.f;

    for (int t = blockIdx.x; t < ntiles; t += gridDim.x) {
        // ---- Stage row tile, duplicated {x,x}: 2 float4 per thread ----
        const float4* xsrc =
            reinterpret_cast<const float4*>(x + (size_t)t * TILE_R * DDIM);
        #pragma unroll
        for (int idx = tid; idx < TILE_R * (DDIM / 4); idx += TPB) {
            float4 v = xsrc[idx];
            ull* dst = xd + idx * 4;
            dst[0] = f32x2_dup(v.x);
            dst[1] = f32x2_dup(v.y);
            dst[2] = f32x2_dup(v.z);
            dst[3] = f32x2_dup(v.w);
        }
        __syncthreads();

        // ---- Main loop: a[r][m] = dot partials for (row w*4+r, codes 2p,2p+1)
        const ulonglong2* xdr2 =
            reinterpret_cast<const ulonglong2*>(xd + (w * TROWS) * DDIM);
        // xdr2[r*32 + i/2] = { {x_i,x_i}, {x_{i+1},x_{i+1}} }

        ull a[TROWS][TPAIRS];
        #pragma unroll
        for (int r = 0; r < TROWS; r++)
            #pragma unroll
            for (int m = 0; m < TPAIRS; m++) a[r][m] = 0ull;

        #pragma unroll 4
        for (int ih = 0; ih < DDIM / 2; ih++) {        // two dims per step
            const ull* cb0 = cbp + (2 * ih)     * (KCODES / 2) + lane;
            const ull* cb1 = cbp + (2 * ih + 1) * (KCODES / 2) + lane;
            ull c0[TPAIRS], c1[TPAIRS];
            #pragma unroll
            for (int m = 0; m < TPAIRS; m++) { c0[m] = cb0[32 * m]; }
            #pragma unroll
            for (int m = 0; m < TPAIRS; m++) { c1[m] = cb1[32 * m]; }
            ulonglong2 xr[TROWS];
            #pragma unroll
            for (int r = 0; r < TROWS; r++) xr[r] = xdr2[r * 32 + ih];
            #pragma unroll
            for (int r = 0; r < TROWS; r++) {
                #pragma unroll
                for (int m = 0; m < TPAIRS; m++) {
                    a[r][m] = ffma2(xr[r].x, c0[m], a[r][m]);
                    a[r][m] = ffma2(xr[r].y, c1[m], a[r][m]);
                }
            }
        }

        // ---- Per-row argmin over all 512 codes (warp-local) + epilogue ----
        #pragma unroll 1
        for (int r = 0; r < TROWS; r++) {
            int grow = t * TILE_R + w * TROWS + r;

            float best = 3.402823466e38f;
            int   bi   = 0;
            #pragma unroll
            for (int m = 0; m < TPAIRS; m++) {
                int p = lane + 32 * m;
                float2 dot = as_float2(a[r][m]);
                float2 q   = scq2[p];
                float s0 = fmaf(-2.f, dot.x, q.x);
                float s1 = fmaf(-2.f, dot.y, q.y);
                if (s0 < best) { best = s0; bi = 2 * p; }
                if (s1 < best) { best = s1; bi = 2 * p + 1; }
            }
            #pragma unroll
            for (int off = 16; off; off >>= 1) {
                float ob = __shfl_xor_sync(0xffffffffu, best, off);
                int   oi = __shfl_xor_sync(0xffffffffu, bi, off);
                if (ob < best || (ob == best && oi < bi)) { best = ob; bi = oi; }
            }

            if (lane == 0) out_idx[grow] = (float)bi;

            // quantize + loss: 2 dims/lane; x from staged smem, c from gmem (L2)
            int lr = w * TROWS + r;
            float xv0 = as_float2(xd[lr * DDIM + 2 * lane]).x;
            float xv1 = as_float2(xd[lr * DDIM + 2 * lane + 1]).x;
            const float2 cv =
                *(reinterpret_cast<const float2*>(cb + (size_t)bi * DDIM) + lane);
            float o0 = xv0 + (cv.x - xv0);
            float o1 = xv1 + (cv.y - xv1);
            float t0 = o0 - xv0; lsum = fmaf(t0, t0, lsum);
            float t1 = o1 - xv1; lsum = fmaf(t1, t1, lsum);
            float* oq = out_q + (size_t)grow * DDIM + 2 * lane;
            oq[0] = o0;   // out_q only 4B-aligned: scalar stores
            oq[1] = o1;
        }
        __syncthreads();   // xd reused next tile
    }

    // ---- Loss: block reduce -> double partial; last block finalizes ----
    __shared__ float warp_sums[TPB / 32];
    #pragma unroll
    for (int off = 16; off; off >>= 1)
        lsum += __shfl_down_sync(0xffffffffu, lsum, off);
    if (lane == 0) warp_sums[w] = lsum;
    __syncthreads();
    if (tid == 0) {
        float b = 0.f;
        #pragma unroll
        for (int i = 0; i < TPB / 32; i++) b += warp_sums[i];
        g_partials[blockIdx.x] = (double)b;
        __threadfence();
        unsigned done = atomicAdd(&g_done, 1u);
        if (done == gridDim.x - 1) {
            double total = 0.0;
            for (int k = 0; k < gridDim.x; k++) total += g_partials[k];
            out[0] = (float)(total * 1.25 / ((double)nrows * DDIM));
            __threadfence();
            g_done = 0;   // self-reset for graph replay
        }
    }
}

extern "C" void kernel_launch(void* const* d_in, const int* in_sizes, int n_in,
                              void* d_out, int out_size)
{
    const float* x  = (const float*)d_in[0];   // inputs  [128,32,32,64]
    const float* cb = (const float*)d_in[1];   // codebook [512,64]
    const int n_elem = in_sizes[0];            // 8388608
    const int nrows  = n_elem / DDIM;          // 131072

    const int smem_bytes = KCODES * DDIM * 4      // cbTf 128KB
                         + TILE_R * DDIM * 8      // xd    32KB
                         + KCODES * 4;            // scq    2KB
    cudaFuncSetAttribute(vq_kernel,
                         cudaFuncAttributeMaxDynamicSharedMemorySize, smem_bytes);

    int sms = 148;
    cudaDeviceGetAttribute(&sms, cudaDevAttrMultiProcessorCount, 0);
    if (sms > MAXBLK) sms = MAXBLK;

    vq_kernel<<<sms, TPB, smem_bytes>>>(x, cb, (float*)d_out, nrows);
}

// round 6
// speedup vs baseline: 1.4508x; 1.4508x over previous
#include <cuda_runtime.h>

// QuantizedCodebook (VQ-VAE): N=131072 rows, D=64, K=512.
// out layout (confirmed): [loss(1) | quantize(N*D) | indices(N)] fp32.
// 2 rows/thread in registers (f32x2 natural pairs); codebook broadcast from smem.
// 16B LDS feeds 4 FFMA2  ->  4 B per FFMA2 (half of R3's operand stream).

#define KCODES 512
#define DDIM   64
#define TPB    256
#define MAXBLK 512

typedef unsigned long long ull;

__device__ double   g_partials[MAXBLK];
__device__ unsigned g_done;   // zero-init; last block resets each run

__device__ __forceinline__ ull ffma2(ull a, ull b, ull c) {
    ull d; asm("fma.rn.f32x2 %0, %1, %2, %3;" : "=l"(d) : "l"(a), "l"(b), "l"(c));
    return d;
}
__device__ __forceinline__ float2 as_float2(ull a) {
    float2 f; asm("mov.b64 {%0, %1}, %2;" : "=f"(f.x), "=f"(f.y) : "l"(a));
    return f;
}

__global__ void __launch_bounds__(TPB, 1)
vq_kernel(const float* __restrict__ x, const float* __restrict__ cb,
          float* __restrict__ out, int nrows)
{
    extern __shared__ float smem[];
    float* scb = smem;                 // [K][D] plain row-major (128 KB)
    float* scq = smem + KCODES * DDIM; // ||c_j||^2 (2 KB)

    float* out_q   = out + 1;
    float* out_idx = out + 1 + (size_t)nrows * DDIM;

    const int tid = threadIdx.x;

    // ---- One-time: codebook + ||c||^2 into smem ----
    for (int idx = tid; idx < KCODES * DDIM; idx += TPB)
        scb[idx] = cb[idx];
    __syncthreads();
    for (int c = tid; c < KCODES; c += TPB) {
        const float* cr = scb + c * DDIM;
        float s = 0.f;
        #pragma unroll
        for (int i = 0; i < DDIM; i++) s = fmaf(cr[i], cr[i], s);
        scq[c] = s;
    }
    __syncthreads();

    // ---- Work split in whole row-pairs (nrows even) ----
    const int npairs = nrows >> 1;                     // 65536
    const int nb     = gridDim.x;
    const int sp = (int)(((long long)blockIdx.x * npairs) / nb);
    const int ep = (int)(((long long)(blockIdx.x + 1) * npairs) / nb);

    float lsum = 0.f;

    for (int p = sp + tid; p < ep; p += TPB) {
        const int r0 = 2 * p;

        // Two rows in registers as natural f32x2 pairs (64 regs total).
        const ulonglong2* xr =
            reinterpret_cast<const ulonglong2*>(x + (size_t)r0 * DDIM);
        ull xa[DDIM / 2], xb[DDIM / 2];
        #pragma unroll
        for (int i = 0; i < DDIM / 4; i++) {
            ulonglong2 v = xr[i];
            xa[2 * i] = v.x; xa[2 * i + 1] = v.y;
        }
        #pragma unroll
        for (int i = 0; i < DDIM / 4; i++) {
            ulonglong2 v = xr[DDIM / 4 + i];
            xb[2 * i] = v.x; xb[2 * i + 1] = v.y;
        }

        float bestA = 3.402823466e38f, bestB = 3.402823466e38f;
        int   biA = 0, biB = 0;

        // 4 codes per step; each 16B code load feeds 4 FFMA2 (2 dims x 2 rows).
        #pragma unroll 1
        for (int j = 0; j < KCODES; j += 4) {
            const ulonglong2* cp =
                reinterpret_cast<const ulonglong2*>(scb + j * DDIM);
            // code k, chunk i -> cp[k*16 + i], 4 dims per chunk
            ull A0 = 0, A1 = 0, A2 = 0, A3 = 0;
            ull B0 = 0, B1 = 0, B2 = 0, B3 = 0;
            #pragma unroll
            for (int i = 0; i < DDIM / 4; i++) {
                ull x0 = xa[2 * i], x1 = xa[2 * i + 1];
                ull y0 = xb[2 * i], y1 = xb[2 * i + 1];
                ulonglong2 q0 = cp[0 * 16 + i];
                A0 = ffma2(x0, q0.x, A0); A0 = ffma2(x1, q0.y, A0);
                B0 = ffma2(y0, q0.x, B0); B0 = ffma2(y1, q0.y, B0);
                ulonglong2 q1 = cp[1 * 16 + i];
                A1 = ffma2(x0, q1.x, A1); A1 = ffma2(x1, q1.y, A1);
                B1 = ffma2(y0, q1.x, B1); B1 = ffma2(y1, q1.y, B1);
                ulonglong2 q2 = cp[2 * 16 + i];
                A2 = ffma2(x0, q2.x, A2); A2 = ffma2(x1, q2.y, A2);
                B2 = ffma2(y0, q2.x, B2); B2 = ffma2(y1, q2.y, B2);
                ulonglong2 q3 = cp[3 * 16 + i];
                A3 = ffma2(x0, q3.x, A3); A3 = ffma2(x1, q3.y, A3);
                B3 = ffma2(y0, q3.x, B3); B3 = ffma2(y1, q3.y, B3);
            }
            float2 fa0 = as_float2(A0), fa1 = as_float2(A1);
            float2 fa2 = as_float2(A2), fa3 = as_float2(A3);
            float2 fb0 = as_float2(B0), fb1 = as_float2(B1);
            float2 fb2 = as_float2(B2), fb3 = as_float2(B3);
            float sa0 = fmaf(-2.f, fa0.x + fa0.y, scq[j + 0]);
            float sa1 = fmaf(-2.f, fa1.x + fa1.y, scq[j + 1]);
            float sa2 = fmaf(-2.f, fa2.x + fa2.y, scq[j + 2]);
            float sa3 = fmaf(-2.f, fa3.x + fa3.y, scq[j + 3]);
            float sb0 = fmaf(-2.f, fb0.x + fb0.y, scq[j + 0]);
            float sb1 = fmaf(-2.f, fb1.x + fb1.y, scq[j + 1]);
            float sb2 = fmaf(-2.f, fb2.x + fb2.y, scq[j + 2]);
            float sb3 = fmaf(-2.f, fb3.x + fb3.y, scq[j + 3]);
            // ascending strict < == jnp.argmin first-min
            if (sa0 < bestA) { bestA = sa0; biA = j + 0; }
            if (sa1 < bestA) { bestA = sa1; biA = j + 1; }
            if (sa2 < bestA) { bestA = sa2; biA = j + 2; }
            if (sa3 < bestA) { bestA = sa3; biA = j + 3; }
            if (sb0 < bestB) { bestB = sb0; biB = j + 0; }
            if (sb1 < bestB) { bestB = sb1; biB = j + 1; }
            if (sb2 < bestB) { bestB = sb2; biB = j + 2; }
            if (sb3 < bestB) { bestB = sb3; biB = j + 3; }
        }

        // ---- Epilogue row A ----
        out_idx[r0] = (float)biA;
        {
            const float4* crow =
                reinterpret_cast<const float4*>(scb + (size_t)biA * DDIM);
            float* oq = out_q + (size_t)r0 * DDIM;   // 4B-aligned: scalar stores
            #pragma unroll
            for (int i = 0; i < DDIM / 4; i++) {
                float4 cv = crow[i];
                float2 u = as_float2(xa[2 * i]);
                float2 v = as_float2(xa[2 * i + 1]);
                float o0 = u.x + (cv.x - u.x);
                float o1 = u.y + (cv.y - u.y);
                float o2 = v.x + (cv.z - v.x);
                float o3 = v.y + (cv.w - v.y);
                float t0 = o0 - u.x; lsum = fmaf(t0, t0, lsum);
                float t1 = o1 - u.y; lsum = fmaf(t1, t1, lsum);
                float t2 = o2 - v.x; lsum = fmaf(t2, t2, lsum);
                float t3 = o3 - v.y; lsum = fmaf(t3, t3, lsum);
                oq[4 * i + 0] = o0; oq[4 * i + 1] = o1;
                oq[4 * i + 2] = o2; oq[4 * i + 3] = o3;
            }
        }
        // ---- Epilogue row B ----
        out_idx[r0 + 1] = (float)biB;
        {
            const float4* crow =
                reinterpret_cast<const float4*>(scb + (size_t)biB * DDIM);
            float* oq = out_q + (size_t)(r0 + 1) * DDIM;
            #pragma unroll
            for (int i = 0; i < DDIM / 4; i++) {
                float4 cv = crow[i];
                float2 u = as_float2(xb[2 * i]);
                float2 v = as_float2(xb[2 * i + 1]);
                float o0 = u.x + (cv.x - u.x);
                float o1 = u.y + (cv.y - u.y);
                float o2 = v.x + (cv.z - v.x);
                float o3 = v.y + (cv.w - v.y);
                float t0 = o0 - u.x; lsum = fmaf(t0, t0, lsum);
                float t1 = o1 - u.y; lsum = fmaf(t1, t1, lsum);
                float t2 = o2 - v.x; lsum = fmaf(t2, t2, lsum);
                float t3 = o3 - v.y; lsum = fmaf(t3, t3, lsum);
                oq[4 * i + 0] = o0; oq[4 * i + 1] = o1;
                oq[4 * i + 2] = o2; oq[4 * i + 3] = o3;
            }
        }
    }

    // ---- Loss: block reduce -> double partial; last block finalizes ----
    __shared__ float warp_sums[TPB / 32];
    #pragma unroll
    for (int off = 16; off; off >>= 1)
        lsum += __shfl_down_sync(0xffffffffu, lsum, off);
    if ((tid & 31) == 0) warp_sums[tid >> 5] = lsum;
    __syncthreads();
    if (tid == 0) {
        float b = 0.f;
        #pragma unroll
        for (int i = 0; i < TPB / 32; i++) b += warp_sums[i];
        g_partials[blockIdx.x] = (double)b;
        __threadfence();
        unsigned done = atomicAdd(&g_done, 1u);
        if (done == gridDim.x - 1) {
            double total = 0.0;
            for (int k = 0; k < gridDim.x; k++) total += g_partials[k];
            out[0] = (float)(total * 1.25 / ((double)nrows * DDIM));
            __threadfence();
            g_done = 0;   // self-reset for graph replay
        }
    }
}

extern "C" void kernel_launch(void* const* d_in, const int* in_sizes, int n_in,
                              void* d_out, int out_size)
{
    const float* x  = (const float*)d_in[0];   // inputs  [128,32,32,64]
    const float* cb = (const float*)d_in[1];   // codebook [512,64]
    const int n_elem = in_sizes[0];            // 8388608
    const int nrows  = n_elem / DDIM;          // 131072

    const int smem_bytes = (KCODES * DDIM + KCODES) * (int)sizeof(float);
    cudaFuncSetAttribute(vq_kernel,
                         cudaFuncAttributeMaxDynamicSharedMemorySize, smem_bytes);

    int sms = 148;
    cudaDeviceGetAttribute(&sms, cudaDevAttrMultiProcessorCount, 0);
    if (sms > MAXBLK) sms = MAXBLK;

    vq_kernel<<<sms, TPB, smem_bytes>>>(x, cb, (float*)d_out, nrows);
}

// round 7
// speedup vs baseline: 2.0338x; 1.4018x over previous
#include <cuda_runtime.h>
#include <cstdint>

// QuantizedCodebook (VQ-VAE): N=131072 rows, D=64, K=512.
// out layout (confirmed): [loss(1) | quantize(N*D) | indices(N)] fp32.
// Distances via tf32x3-split mma.sync (m16n8k8); exact fp32 quantize/loss epilogue.

#define KCODES 512
#define DDIM   64
#define TPB    256
#define NWARP  (TPB / 32)
#define HALF_K 256          // codes per pass (smem limit for hi+lo split)
#define PITCH  264          // 256 + 8 pad -> conflict-free fragment LDS
#define MAXBLK 512
#define NROWS  131072

typedef uint32_t u32;

__device__ double   g_partials[MAXBLK];
__device__ unsigned g_done;           // zero-init; last block resets each run
__device__ float    g_best[NROWS];    // per-row running best (between passes)
__device__ int      g_bidx[NROWS];    // per-row running argmin

__device__ __forceinline__ u32 to_tf32(float f) {
    u32 u; asm("cvt.rna.tf32.f32 %0, %1;" : "=r"(u) : "f"(f)); return u;
}
__device__ __forceinline__ void mma_tf32(float c[4], const u32 a[4], u32 b0, u32 b1) {
    asm("mma.sync.aligned.m16n8k8.row.col.f32.tf32.tf32.f32 "
        "{%0,%1,%2,%3}, {%4,%5,%6,%7}, {%8,%9}, {%0,%1,%2,%3};"
        : "+f"(c[0]), "+f"(c[1]), "+f"(c[2]), "+f"(c[3])
        : "r"(a[0]), "r"(a[1]), "r"(a[2]), "r"(a[3]), "r"(b0), "r"(b1));
}

__global__ void __launch_bounds__(TPB, 1)
vq_kernel(const float* __restrict__ x, const float* __restrict__ cb,
          float* __restrict__ out, int nrows)
{
    // dynamic smem: Bh[64][PITCH] u32 | Bl[64][PITCH] u32 | scq[512] float
    extern __shared__ unsigned char smraw[];
    u32*   Bh  = (u32*)smraw;
    u32*   Bl  = Bh + DDIM * PITCH;
    float* scq = (float*)(Bl + DDIM * PITCH);
    __shared__ int sidx[NWARP][32];

    float* out_q   = out + 1;
    float* out_idx = out + 1 + (size_t)nrows * DDIM;

    const int tid  = threadIdx.x;
    const int w    = tid >> 5;
    const int lane = tid & 31;
    const int g4   = lane >> 2;   // groupID 0..7
    const int q    = lane & 3;    // threadID-in-group 0..3

    // ---- ||c||^2 (exact fp32, same order as R6) ----
    for (int c = tid; c < KCODES; c += TPB) {
        const float* cr = cb + c * DDIM;
        float s = 0.f;
        #pragma unroll
        for (int i = 0; i < DDIM; i++) s = fmaf(cr[i], cr[i], s);
        scq[c] = s;
    }

    // ---- row-group split: groups of 32 rows ----
    const int ng = nrows >> 5;                               // 4096
    const int gs = (int)(((long long)blockIdx.x * ng) / gridDim.x);
    const int ge = (int)(((long long)(blockIdx.x + 1) * ng) / gridDim.x);

    float lsum = 0.f;

    #pragma unroll 1
    for (int p = 0; p < 2; p++) {
        const int pb = p * HALF_K;

        // ---- stage codebook half: k-major, tf32 hi/lo split ----
        __syncthreads();   // previous pass finished reading Bh/Bl
        for (int idx = tid; idx < HALF_K * DDIM; idx += TPB) {
            int c = idx >> 6;          // 0..255
            int k = idx & 63;
            float v = cb[(pb + c) * DDIM + k];
            u32 h = to_tf32(v);
            Bh[k * PITCH + c] = h;
            Bl[k * PITCH + c] = to_tf32(v - __uint_as_float(h));
        }
        __syncthreads();

        #pragma unroll 1
        for (int g = gs + w; g < ge; g += NWARP) {
            const int R = g << 5;     // 32 rows per group

            // ---- A fragments (2 subtiles x 8 ksteps x 4 regs), hi+lo ----
            u32 ah[2][8][4], al[2][8][4];
            #pragma unroll
            for (int s = 0; s < 2; s++)
                #pragma unroll
                for (int t = 0; t < 8; t++)
                    #pragma unroll
                    for (int rg = 0; rg < 4; rg++) {
                        int row = R + 16 * s + g4 + (rg & 1) * 8;
                        int col = 8 * t + q + (rg >> 1) * 4;
                        float v = x[(size_t)row * DDIM + col];
                        u32 h = to_tf32(v);
                        ah[s][t][rg] = h;
                        al[s][t][rg] = to_tf32(v - __uint_as_float(h));
                    }

            // rows visible to this thread
            const int rows0 = R + g4, rows1 = R + 8 + g4;
            const int rows2 = R + 16 + g4, rows3 = R + 24 + g4;

            float best[4]; int bx[4];
            if (p == 0) {
                best[0] = best[1] = best[2] = best[3] = 3.402823466e38f;
                bx[0] = bx[1] = bx[2] = bx[3] = 0;
            } else {
                best[0] = g_best[rows0]; bx[0] = g_bidx[rows0];
                best[1] = g_best[rows1]; bx[1] = g_bidx[rows1];
                best[2] = g_best[rows2]; bx[2] = g_bidx[rows2];
                best[3] = g_best[rows3]; bx[3] = g_bidx[rows3];
            }

            // ---- ntiles: 8 codes each ----
            #pragma unroll 1
            for (int n = 0; n < HALF_K / 8; n++) {
                float cA[4] = {0.f, 0.f, 0.f, 0.f};
                float cB[4] = {0.f, 0.f, 0.f, 0.f};
                #pragma unroll
                for (int t = 0; t < 8; t++) {
                    const u32* hp = Bh + (8 * t + q) * PITCH + 8 * n + g4;
                    const u32* lp = Bl + (8 * t + q) * PITCH + 8 * n + g4;
                    u32 bh0 = hp[0], bh1 = hp[4 * PITCH];
                    u32 bl0 = lp[0], bl1 = lp[4 * PITCH];
                    mma_tf32(cA, ah[0][t], bh0, bh1);
                    mma_tf32(cA, al[0][t], bh0, bh1);
                    mma_tf32(cA, ah[0][t], bl0, bl1);
                    mma_tf32(cB, ah[1][t], bh0, bh1);
                    mma_tf32(cB, al[1][t], bh0, bh1);
                    mma_tf32(cB, ah[1][t], bl0, bl1);
                }
                int code0 = pb + 8 * n + 2 * q;
                float2 sq = *(const float2*)(scq + code0);
                float d;
                d = fmaf(-2.f, cA[0], sq.x);
                if (d < best[0]) { best[0] = d; bx[0] = code0; }
                d = fmaf(-2.f, cA[1], sq.y);
                if (d < best[0]) { best[0] = d; bx[0] = code0 + 1; }
                d = fmaf(-2.f, cA[2], sq.x);
                if (d < best[1]) { best[1] = d; bx[1] = code0; }
                d = fmaf(-2.f, cA[3], sq.y);
                if (d < best[1]) { best[1] = d; bx[1] = code0 + 1; }
                d = fmaf(-2.f, cB[0], sq.x);
                if (d < best[2]) { best[2] = d; bx[2] = code0; }
                d = fmaf(-2.f, cB[1], sq.y);
                if (d < best[2]) { best[2] = d; bx[2] = code0 + 1; }
                d = fmaf(-2.f, cB[2], sq.x);
                if (d < best[3]) { best[3] = d; bx[3] = code0; }
                d = fmaf(-2.f, cB[3], sq.y);
                if (d < best[3]) { best[3] = d; bx[3] = code0 + 1; }
            }

            // ---- quad reduce (lanes differing in q): min with first-index tie ----
            #pragma unroll
            for (int j = 0; j < 4; j++) {
                #pragma unroll
                for (int off = 1; off <= 2; off <<= 1) {
                    float ob = __shfl_xor_sync(0xffffffffu, best[j], off);
                    int   oi = __shfl_xor_sync(0xffffffffu, bx[j], off);
                    if (ob < best[j] || (ob == best[j] && oi < bx[j])) {
                        best[j] = ob; bx[j] = oi;
                    }
                }
            }

            if (p == 0) {
                if (q == 0) {
                    g_best[rows0] = best[0]; g_bidx[rows0] = bx[0];
                    g_best[rows1] = best[1]; g_bidx[rows1] = bx[1];
                    g_best[rows2] = best[2]; g_bidx[rows2] = bx[2];
                    g_best[rows3] = best[3]; g_bidx[rows3] = bx[3];
                }
            } else {
                if (q == 0) {
                    out_idx[rows0] = (float)bx[0]; sidx[w][g4]      = bx[0];
                    out_idx[rows1] = (float)bx[1]; sidx[w][g4 + 8]  = bx[1];
                    out_idx[rows2] = (float)bx[2]; sidx[w][g4 + 16] = bx[2];
                    out_idx[rows3] = (float)bx[3]; sidx[w][g4 + 24] = bx[3];
                }
                __syncwarp();
                // exact fp32 quantize + loss (same math as R6)
                #pragma unroll 1
                for (int r = 0; r < 32; r++) {
                    int bi  = sidx[w][r];
                    int row = R + r;
                    float2 xv = *(const float2*)(x  + (size_t)row * DDIM + 2 * lane);
                    float2 cv = *(const float2*)(cb + (size_t)bi  * DDIM + 2 * lane);
                    float o0 = xv.x + (cv.x - xv.x);
                    float o1 = xv.y + (cv.y - xv.y);
                    float t0 = o0 - xv.x; lsum = fmaf(t0, t0, lsum);
                    float t1 = o1 - xv.y; lsum = fmaf(t1, t1, lsum);
                    float* oq = out_q + (size_t)row * DDIM + 2 * lane;
                    oq[0] = o0;   // out_q only 4B-aligned: scalar stores
                    oq[1] = o1;
                }
            }
        }
    }

    // ---- loss: block reduce -> double partial; last block finalizes ----
    __shared__ float warp_sums[NWARP];
    #pragma unroll
    for (int off = 16; off; off >>= 1)
        lsum += __shfl_down_sync(0xffffffffu, lsum, off);
    if (lane == 0) warp_sums[w] = lsum;
    __syncthreads();
    if (tid == 0) {
        float b = 0.f;
        #pragma unroll
        for (int i = 0; i < NWARP; i++) b += warp_sums[i];
        g_partials[blockIdx.x] = (double)b;
        __threadfence();
        unsigned done = atomicAdd(&g_done, 1u);
        if (done == gridDim.x - 1) {
            double total = 0.0;
            for (int k = 0; k < gridDim.x; k++) total += g_partials[k];
            out[0] = (float)(total * 1.25 / ((double)nrows * DDIM));
            __threadfence();
            g_done = 0;   // self-reset for graph replay
        }
    }
}

extern "C" void kernel_launch(void* const* d_in, const int* in_sizes, int n_in,
                              void* d_out, int out_size)
{
    const float* x  = (const float*)d_in[0];   // inputs  [128,32,32,64]
    const float* cb = (const float*)d_in[1];   // codebook [512,64]
    const int n_elem = in_sizes[0];            // 8388608
    const int nrows  = n_elem / DDIM;          // 131072

    const int smem_bytes = (2 * DDIM * PITCH) * 4 + KCODES * 4;   // ~137 KB
    cudaFuncSetAttribute(vq_kernel,
                         cudaFuncAttributeMaxDynamicSharedMemorySize, smem_bytes);

    int sms = 148;
    cudaDeviceGetAttribute(&sms, cudaDevAttrMultiProcessorCount, 0);
    if (sms > MAXBLK) sms = MAXBLK;

    vq_kernel<<<sms, TPB, smem_bytes>>>(x, cb, (float*)d_out, nrows);
}

// round 8
// speedup vs baseline: 2.1825x; 1.0731x over previous
#include <cuda_runtime.h>
#include <cstdint>

// QuantizedCodebook (VQ-VAE): N=131072 rows, D=64, K=512.
// out layout (confirmed): [loss(1) | quantize(N*D) | indices(N)] fp32.
// tf32x3-split mma.sync m16n8k8; 16 warps/SM, 16 rows/warp, 3 indep mma chains.

#define KCODES 512
#define DDIM   64
#define TPB    512
#define NWARP  (TPB / 32)
#define HALF_K 256          // codes per pass (smem limit for hi+lo split)
#define PITCH  264          // 256 + 8 pad -> conflict-free fragment LDS
#define MAXBLK 512
#define NROWS  131072

typedef uint32_t u32;

__device__ double   g_partials[MAXBLK];
__device__ unsigned g_done;           // zero-init; last block resets each run
__device__ float    g_best[NROWS];    // per-row running best (between passes)
__device__ int      g_bidx[NROWS];    // per-row running argmin

__device__ __forceinline__ u32 to_tf32(float f) {
    u32 u; asm("cvt.rna.tf32.f32 %0, %1;" : "=r"(u) : "f"(f)); return u;
}
__device__ __forceinline__ void mma_tf32(float c[4], const u32 a[4], u32 b0, u32 b1) {
    asm("mma.sync.aligned.m16n8k8.row.col.f32.tf32.tf32.f32 "
        "{%0,%1,%2,%3}, {%4,%5,%6,%7}, {%8,%9}, {%0,%1,%2,%3};"
        : "+f"(c[0]), "+f"(c[1]), "+f"(c[2]), "+f"(c[3])
        : "r"(a[0]), "r"(a[1]), "r"(a[2]), "r"(a[3]), "r"(b0), "r"(b1));
}

__global__ void __launch_bounds__(TPB, 1)
vq_kernel(const float* __restrict__ x, const float* __restrict__ cb,
          float* __restrict__ out, int nrows)
{
    // dynamic smem: Bh[64][PITCH] u32 | Bl[64][PITCH] u32 | scq[512] float
    extern __shared__ unsigned char smraw[];
    u32*   Bh  = (u32*)smraw;
    u32*   Bl  = Bh + DDIM * PITCH;
    float* scq = (float*)(Bl + DDIM * PITCH);
    __shared__ int sidx[NWARP][16];

    float* out_q   = out + 1;
    float* out_idx = out + 1 + (size_t)nrows * DDIM;

    const int tid  = threadIdx.x;
    const int w    = tid >> 5;
    const int lane = tid & 31;
    const int g4   = lane >> 2;   // groupID 0..7
    const int q    = lane & 3;    // threadID-in-group 0..3

    // ---- ||c||^2 (exact fp32) ----
    for (int c = tid; c < KCODES; c += TPB) {
        const float* cr = cb + c * DDIM;
        float s = 0.f;
        #pragma unroll
        for (int i = 0; i < DDIM; i++) s = fmaf(cr[i], cr[i], s);
        scq[c] = s;
    }

    // ---- row-group split: groups of 16 rows ----
    const int ng = nrows >> 4;                               // 8192
    const int gs = (int)(((long long)blockIdx.x * ng) / gridDim.x);
    const int ge = (int)(((long long)(blockIdx.x + 1) * ng) / gridDim.x);

    float lsum = 0.f;

    #pragma unroll 1
    for (int p = 0; p < 2; p++) {
        const int pb = p * HALF_K;

        // ---- stage codebook half: k-major, tf32 hi/lo split ----
        __syncthreads();   // previous pass finished reading Bh/Bl
        for (int idx = tid; idx < HALF_K * DDIM; idx += TPB) {
            int c = idx >> 6;          // 0..255
            int k = idx & 63;
            float v = cb[(pb + c) * DDIM + k];
            u32 h = to_tf32(v);
            Bh[k * PITCH + c] = h;
            Bl[k * PITCH + c] = to_tf32(v - __uint_as_float(h));
        }
        __syncthreads();

        #pragma unroll 1
        for (int g = gs + w; g < ge; g += NWARP) {
            const int R = g << 4;     // 16 rows per group

            // ---- A fragments (8 ksteps x 4 regs), hi+lo: 64 regs ----
            u32 ah[8][4], al[8][4];
            #pragma unroll
            for (int t = 0; t < 8; t++)
                #pragma unroll
                for (int rg = 0; rg < 4; rg++) {
                    int row = R + g4 + (rg & 1) * 8;
                    int col = 8 * t + q + (rg >> 1) * 4;
                    float v = x[(size_t)row * DDIM + col];
                    u32 h = to_tf32(v);
                    ah[t][rg] = h;
                    al[t][rg] = to_tf32(v - __uint_as_float(h));
                }

            const int rows0 = R + g4, rows1 = R + 8 + g4;

            float best[2]; int bx[2];
            if (p == 0) {
                best[0] = best[1] = 3.402823466e38f;
                bx[0] = bx[1] = 0;
            } else {
                best[0] = g_best[rows0]; bx[0] = g_bidx[rows0];
                best[1] = g_best[rows1]; bx[1] = g_bidx[rows1];
            }

            // ---- n-tiles: 8 codes each; 3 independent mma chains ----
            #pragma unroll 1
            for (int n = 0; n < HALF_K / 8; n++) {
                float c1[4] = {0.f, 0.f, 0.f, 0.f};   // ah*bh
                float c2[4] = {0.f, 0.f, 0.f, 0.f};   // al*bh
                float c3[4] = {0.f, 0.f, 0.f, 0.f};   // ah*bl
                #pragma unroll
                for (int t = 0; t < 8; t++) {
                    const u32* hp = Bh + (8 * t + q) * PITCH + 8 * n + g4;
                    const u32* lp = Bl + (8 * t + q) * PITCH + 8 * n + g4;
                    u32 bh0 = hp[0], bh1 = hp[4 * PITCH];
                    u32 bl0 = lp[0], bl1 = lp[4 * PITCH];
                    mma_tf32(c1, ah[t], bh0, bh1);
                    mma_tf32(c2, al[t], bh0, bh1);
                    mma_tf32(c3, ah[t], bl0, bl1);
                }
                int code0 = pb + 8 * n + 2 * q;
                float2 sq = *(const float2*)(scq + code0);
                float d;
                d = fmaf(-2.f, c1[0] + c2[0] + c3[0], sq.x);
                if (d < best[0]) { best[0] = d; bx[0] = code0; }
                d = fmaf(-2.f, c1[1] + c2[1] + c3[1], sq.y);
                if (d < best[0]) { best[0] = d; bx[0] = code0 + 1; }
                d = fmaf(-2.f, c1[2] + c2[2] + c3[2], sq.x);
                if (d < best[1]) { best[1] = d; bx[1] = code0; }
                d = fmaf(-2.f, c1[3] + c2[3] + c3[3], sq.y);
                if (d < best[1]) { best[1] = d; bx[1] = code0 + 1; }
            }

            // ---- quad reduce (lanes differing in q), first-index tie ----
            #pragma unroll
            for (int j = 0; j < 2; j++) {
                #pragma unroll
                for (int off = 1; off <= 2; off <<= 1) {
                    float ob = __shfl_xor_sync(0xffffffffu, best[j], off);
                    int   oi = __shfl_xor_sync(0xffffffffu, bx[j], off);
                    if (ob < best[j] || (ob == best[j] && oi < bx[j])) {
                        best[j] = ob; bx[j] = oi;
                    }
                }
            }

            if (p == 0) {
                if (q == 0) {
                    g_best[rows0] = best[0]; g_bidx[rows0] = bx[0];
                    g_best[rows1] = best[1]; g_bidx[rows1] = bx[1];
                }
            } else {
                if (q == 0) {
                    out_idx[rows0] = (float)bx[0]; sidx[w][g4]     = bx[0];
                    out_idx[rows1] = (float)bx[1]; sidx[w][g4 + 8] = bx[1];
                }
                __syncwarp();
                // exact fp32 quantize + loss (2 dims/lane)
                #pragma unroll 1
                for (int r = 0; r < 16; r++) {
                    int bi  = sidx[w][r];
                    int row = R + r;
                    float2 xv = *(const float2*)(x  + (size_t)row * DDIM + 2 * lane);
                    float2 cv = *(const float2*)(cb + (size_t)bi  * DDIM + 2 * lane);
                    float o0 = xv.x + (cv.x - xv.x);
                    float o1 = xv.y + (cv.y - xv.y);
                    float t0 = o0 - xv.x; lsum = fmaf(t0, t0, lsum);
                    float t1 = o1 - xv.y; lsum = fmaf(t1, t1, lsum);
                    float* oq = out_q + (size_t)row * DDIM + 2 * lane;
                    oq[0] = o0;   // out_q only 4B-aligned: scalar stores
                    oq[1] = o1;
                }
            }
        }
    }

    // ---- loss: block reduce -> double partial; last block finalizes ----
    __shared__ float warp_sums[NWARP];
    #pragma unroll
    for (int off = 16; off; off >>= 1)
        lsum += __shfl_down_sync(0xffffffffu, lsum, off);
    if (lane == 0) warp_sums[w] = lsum;
    __syncthreads();
    if (tid == 0) {
        float b = 0.f;
        #pragma unroll
        for (int i = 0; i < NWARP; i++) b += warp_sums[i];
        g_partials[blockIdx.x] = (double)b;
        __threadfence();
        unsigned done = atomicAdd(&g_done, 1u);
        if (done == gridDim.x - 1) {
            double total = 0.0;
            for (int k = 0; k < gridDim.x; k++) total += g_partials[k];
            out[0] = (float)(total * 1.25 / ((double)nrows * DDIM));
            __threadfence();
            g_done = 0;   // self-reset for graph replay
        }
    }
}

extern "C" void kernel_launch(void* const* d_in, const int* in_sizes, int n_in,
                              void* d_out, int out_size)
{
    const float* x  = (const float*)d_in[0];   // inputs  [128,32,32,64]
    const float* cb = (const float*)d_in[1];   // codebook [512,64]
    const int n_elem = in_sizes[0];            // 8388608
    const int nrows  = n_elem / DDIM;          // 131072

    const int smem_bytes = (2 * DDIM * PITCH) * 4 + KCODES * 4;   // ~137 KB
    cudaFuncSetAttribute(vq_kernel,
                         cudaFuncAttributeMaxDynamicSharedMemorySize, smem_bytes);

    int sms = 148;
    cudaDeviceGetAttribute(&sms, cudaDevAttrMultiProcessorCount, 0);
    if (sms > MAXBLK) sms = MAXBLK;

    vq_kernel<<<sms, TPB, smem_bytes>>>(x, cb, (float*)d_out, nrows);
}

// round 9
// speedup vs baseline: 2.3200x; 1.0630x over previous
#include <cuda_runtime.h>
#include <cstdint>

// QuantizedCodebook (VQ-VAE): N=131072 rows, D=64, K=512.
// out layout (confirmed): [loss(1) | quantize(N*D) | indices(N)] fp32.
// Distances: tf32 main term (m16n8k8) + fp16 correction terms (m16n8k16):
//   x.c ~= tf32(x).tf32(c)  [tf32 mma, exact products, fp32 accum]
//        + f16(x - tf32(x)) . f16(c)        [fp16 mma]
//        + f16(x) . f16(c - tf32(c))        [fp16 mma]
// total distance error ~2e-6 (same level as the tf32x3 scheme: rel_err 0.0).

#define KCODES 512
#define DDIM   64
#define TPB    512
#define NWARP  (TPB / 32)
#define HALF_K 256          // codes per pass
#define PITCH  264          // 256 + 8 pad -> conflict-free fragment LDS
#define MAXBLK 512
#define NROWS  131072

typedef uint32_t u32;

__device__ double   g_partials[MAXBLK];
__device__ unsigned g_done;           // zero-init; last block resets each run
__device__ float    g_best[NROWS];    // per-row running best (between passes)
__device__ int      g_bidx[NROWS];    // per-row running argmin

__device__ __forceinline__ u32 to_tf32(float f) {
    u32 u; asm("cvt.rna.tf32.f32 %0, %1;" : "=r"(u) : "f"(f)); return u;
}
__device__ __forceinline__ u32 pack_h2(float lo, float hi) {
    // d[15:0] = convert(lo), d[31:16] = convert(hi)  (PTX: cvt d, a, b -> hi=a, lo=b)
    u32 r; asm("cvt.rn.f16x2.f32 %0, %1, %2;" : "=r"(r) : "f"(hi), "f"(lo));
    return r;
}
__device__ __forceinline__ void mma_tf32(float c[4], const u32 a[4], u32 b0, u32 b1) {
    asm("mma.sync.aligned.m16n8k8.row.col.f32.tf32.tf32.f32 "
        "{%0,%1,%2,%3}, {%4,%5,%6,%7}, {%8,%9}, {%0,%1,%2,%3};"
        : "+f"(c[0]), "+f"(c[1]), "+f"(c[2]), "+f"(c[3])
        : "r"(a[0]), "r"(a[1]), "r"(a[2]), "r"(a[3]), "r"(b0), "r"(b1));
}
__device__ __forceinline__ void mma_f16(float c[4], const u32 a[4], u32 b0, u32 b1) {
    asm("mma.sync.aligned.m16n8k16.row.col.f32.f16.f16.f32 "
        "{%0,%1,%2,%3}, {%4,%5,%6,%7}, {%8,%9}, {%0,%1,%2,%3};"
        : "+f"(c[0]), "+f"(c[1]), "+f"(c[2]), "+f"(c[3])
        : "r"(a[0]), "r"(a[1]), "r"(a[2]), "r"(a[3]), "r"(b0), "r"(b1));
}

__global__ void __launch_bounds__(TPB, 1)
vq_kernel(const float* __restrict__ x, const float* __restrict__ cb,
          float* __restrict__ out, int nrows)
{
    // dynamic smem: Bh[64][PITCH] u32 (tf32 of c)
    //             | Bc2[32][PITCH] u32 (f16x2 k-pairs of c)
    //             | Bl2[32][PITCH] u32 (f16x2 k-pairs of c - tf32(c))
    //             | scq[512] float
    extern __shared__ unsigned char smraw[];
    u32*   Bh  = (u32*)smraw;
    u32*   Bc2 = Bh  + DDIM * PITCH;
    u32*   Bl2 = Bc2 + (DDIM / 2) * PITCH;
    float* scq = (float*)(Bl2 + (DDIM / 2) * PITCH);
    __shared__ int sidx[NWARP][16];

    float* out_q   = out + 1;
    float* out_idx = out + 1 + (size_t)nrows * DDIM;

    const int tid  = threadIdx.x;
    const int w    = tid >> 5;
    const int lane = tid & 31;
    const int g4   = lane >> 2;   // groupID 0..7
    const int q    = lane & 3;    // threadID-in-group 0..3

    // ---- ||c||^2 (exact fp32) ----
    for (int c = tid; c < KCODES; c += TPB) {
        const float* cr = cb + c * DDIM;
        float s = 0.f;
        #pragma unroll
        for (int i = 0; i < DDIM; i++) s = fmaf(cr[i], cr[i], s);
        scq[c] = s;
    }

    // ---- row-group split: groups of 16 rows ----
    const int ng = nrows >> 4;                               // 8192
    const int gs = (int)(((long long)blockIdx.x * ng) / gridDim.x);
    const int ge = (int)(((long long)(blockIdx.x + 1) * ng) / gridDim.x);

    float lsum = 0.f;

    #pragma unroll 1
    for (int p = 0; p < 2; p++) {
        const int pb = p * HALF_K;

        // ---- stage codebook half: tf32 hi + f16 full + f16 low ----
        __syncthreads();   // previous pass finished reading B arrays
        for (int idx = tid; idx < HALF_K * (DDIM / 2); idx += TPB) {
            int c  = idx >> 5;          // 0..255
            int kp = idx & 31;          // k-pair 0..31
            const float* src = cb + (size_t)(pb + c) * DDIM + 2 * kp;
            float v0 = src[0], v1 = src[1];
            u32 h0 = to_tf32(v0), h1 = to_tf32(v1);
            Bh[(2 * kp)     * PITCH + c] = h0;
            Bh[(2 * kp + 1) * PITCH + c] = h1;
            Bc2[kp * PITCH + c] = pack_h2(v0, v1);
            Bl2[kp * PITCH + c] =
                pack_h2(v0 - __uint_as_float(h0), v1 - __uint_as_float(h1));
        }
        __syncthreads();

        #pragma unroll 1
        for (int g = gs + w; g < ge; g += NWARP) {
            const int R = g << 4;     // 16 rows per group

            // ---- A fragments ----
            // tf32: ah[t][rg], row g4+8*(rg&1), col 8t+q+4*(rg>>1)
            u32 ah[8][4];
            #pragma unroll
            for (int t = 0; t < 8; t++)
                #pragma unroll
                for (int rg = 0; rg < 4; rg++) {
                    int row = R + g4 + (rg & 1) * 8;
                    int col = 8 * t + q + (rg >> 1) * 4;
                    ah[t][rg] = to_tf32(x[(size_t)row * DDIM + col]);
                }
            // f16 k16: ax = f16(x), axl = f16(x - tf32(x));
            // frag rg: row g4+8*(rg&1), cols 16*t4 + 2q + 8*(rg>>1) .. +1
            u32 ax[4][4], axl[4][4];
            #pragma unroll
            for (int t4 = 0; t4 < 4; t4++)
                #pragma unroll
                for (int rg = 0; rg < 4; rg++) {
                    int row = R + g4 + (rg & 1) * 8;
                    int col = 16 * t4 + 2 * q + (rg >> 1) * 8;
                    float2 v = *(const float2*)(x + (size_t)row * DDIM + col);
                    ax[t4][rg] = pack_h2(v.x, v.y);
                    u32 h0 = to_tf32(v.x), h1 = to_tf32(v.y);
                    axl[t4][rg] = pack_h2(v.x - __uint_as_float(h0),
                                          v.y - __uint_as_float(h1));
                }

            const int rows0 = R + g4, rows1 = R + 8 + g4;

            float best[2]; int bx[2];
            if (p == 0) {
                best[0] = best[1] = 3.402823466e38f;
                bx[0] = bx[1] = 0;
            } else {
                best[0] = g_best[rows0]; bx[0] = g_bidx[rows0];
                best[1] = g_best[rows1]; bx[1] = g_bidx[rows1];
            }

            // ---- n-tiles: 8 codes each; 3 independent chains (8+4+4 mma) ----
            #pragma unroll 1
            for (int n = 0; n < HALF_K / 8; n++) {
                float c1[4] = {0.f, 0.f, 0.f, 0.f};   // tf32 main
                float c2[4] = {0.f, 0.f, 0.f, 0.f};   // f16(xl) . f16(c)
                float c3[4] = {0.f, 0.f, 0.f, 0.f};   // f16(x)  . f16(cl)
                const int nb0 = 8 * n + g4;
                #pragma unroll
                for (int t4 = 0; t4 < 4; t4++) {
                    // two tf32 ksteps per t4 (k = 16t4 .. 16t4+15)
                    u32 bh0 = Bh[(16 * t4 + q)     * PITCH + nb0];
                    u32 bh1 = Bh[(16 * t4 + q + 4) * PITCH + nb0];
                    mma_tf32(c1, ah[2 * t4], bh0, bh1);
                    u32 bc0 = Bc2[(8 * t4 + q)     * PITCH + nb0];
                    u32 bc1 = Bc2[(8 * t4 + q + 4) * PITCH + nb0];
                    mma_f16(c2, axl[t4], bc0, bc1);
                    u32 bh2 = Bh[(16 * t4 + 8 + q)     * PITCH + nb0];
                    u32 bh3 = Bh[(16 * t4 + 8 + q + 4) * PITCH + nb0];
                    mma_tf32(c1, ah[2 * t4 + 1], bh2, bh3);
                    u32 bl0 = Bl2[(8 * t4 + q)     * PITCH + nb0];
                    u32 bl1 = Bl2[(8 * t4 + q + 4) * PITCH + nb0];
                    mma_f16(c3, ax[t4], bl0, bl1);
                }
                int code0 = pb + 8 * n + 2 * q;
                float2 sq = *(const float2*)(scq + code0);
                float d;
                d = fmaf(-2.f, c1[0] + c2[0] + c3[0], sq.x);
                if (d < best[0]) { best[0] = d; bx[0] = code0; }
                d = fmaf(-2.f, c1[1] + c2[1] + c3[1], sq.y);
                if (d < best[0]) { best[0] = d; bx[0] = code0 + 1; }
                d = fmaf(-2.f, c1[2] + c2[2] + c3[2], sq.x);
                if (d < best[1]) { best[1] = d; bx[1] = code0; }
                d = fmaf(-2.f, c1[3] + c2[3] + c3[3], sq.y);
                if (d < best[1]) { best[1] = d; bx[1] = code0 + 1; }
            }

            // ---- quad reduce (lanes differing in q), first-index tie ----
            #pragma unroll
            for (int j = 0; j < 2; j++) {
                #pragma unroll
                for (int off = 1; off <= 2; off <<= 1) {
                    float ob = __shfl_xor_sync(0xffffffffu, best[j], off);
                    int   oi = __shfl_xor_sync(0xffffffffu, bx[j], off);
                    if (ob < best[j] || (ob == best[j] && oi < bx[j])) {
                        best[j] = ob; bx[j] = oi;
                    }
                }
            }

            if (p == 0) {
                if (q == 0) {
                    g_best[rows0] = best[0]; g_bidx[rows0] = bx[0];
                    g_best[rows1] = best[1]; g_bidx[rows1] = bx[1];
                }
            } else {
                if (q == 0) {
                    out_idx[rows0] = (float)bx[0]; sidx[w][g4]     = bx[0];
                    out_idx[rows1] = (float)bx[1]; sidx[w][g4 + 8] = bx[1];
                }
                __syncwarp();
                // exact fp32 quantize + loss (2 dims/lane)
                #pragma unroll 1
                for (int r = 0; r < 16; r++) {
                    int bi  = sidx[w][r];
                    int row = R + r;
                    float2 xv = *(const float2*)(x  + (size_t)row * DDIM + 2 * lane);
                    float2 cv = *(const float2*)(cb + (size_t)bi  * DDIM + 2 * lane);
                    float o0 = xv.x + (cv.x - xv.x);
                    float o1 = xv.y + (cv.y - xv.y);
                    float t0 = o0 - xv.x; lsum = fmaf(t0, t0, lsum);
                    float t1 = o1 - xv.y; lsum = fmaf(t1, t1, lsum);
                    float* oq = out_q + (size_t)row * DDIM + 2 * lane;
                    oq[0] = o0;   // out_q only 4B-aligned: scalar stores
                    oq[1] = o1;
                }
            }
        }
    }

    // ---- loss: block reduce -> double partial; last block finalizes ----
    __shared__ float warp_sums[NWARP];
    #pragma unroll
    for (int off = 16; off; off >>= 1)
        lsum += __shfl_down_sync(0xffffffffu, lsum, off);
    if (lane == 0) warp_sums[w] = lsum;
    __syncthreads();
    if (tid == 0) {
        float b = 0.f;
        #pragma unroll
        for (int i = 0; i < NWARP; i++) b += warp_sums[i];
        g_partials[blockIdx.x] = (double)b;
        __threadfence();
        unsigned done = atomicAdd(&g_done, 1u);
        if (done == gridDim.x - 1) {
            double total = 0.0;
            for (int k = 0; k < gridDim.x; k++) total += g_partials[k];
            out[0] = (float)(total * 1.25 / ((double)nrows * DDIM));
            __threadfence();
            g_done = 0;   // self-reset for graph replay
        }
    }
}

extern "C" void kernel_launch(void* const* d_in, const int* in_sizes, int n_in,
                              void* d_out, int out_size)
{
    const float* x  = (const float*)d_in[0];   // inputs  [128,32,32,64]
    const float* cb = (const float*)d_in[1];   // codebook [512,64]
    const int n_elem = in_sizes[0];            // 8388608
    const int nrows  = n_elem / DDIM;          // 131072

    const int smem_bytes =
        (DDIM * PITCH + (DDIM / 2) * PITCH * 2) * 4 + KCODES * 4;  // ~137 KB
    cudaFuncSetAttribute(vq_kernel,
                         cudaFuncAttributeMaxDynamicSharedMemorySize, smem_bytes);

    int sms = 148;
    cudaDeviceGetAttribute(&sms, cudaDevAttrMultiProcessorCount, 0);
    if (sms > MAXBLK) sms = MAXBLK;

    vq_kernel<<<sms, TPB, smem_bytes>>>(x, cb, (float*)d_out, nrows);
}

// round 10
// speedup vs baseline: 3.2346x; 1.3942x over previous
#include <cuda_runtime.h>
#include <cuda_fp16.h>
#include <cstdint>

// QuantizedCodebook (VQ-VAE): N=131072 rows, D=64, K=512.
// out layout (confirmed): [loss(1) | quantize(N*D) | indices(N)] fp32.
// Distances via fp16 double-split mma (m16n8k16), single pass over 512 codes:
//   x.c ~= h1.c1 + h2.c1 + h1.c2,  h1=f16(x), h2=f16(x-h1), c1=f16(c), c2=f16(c-c1)
// error ~ xc*2^-22 (same level as R9 tf32+f16 scheme: rel_err 0.0).

#define KCODES 512
#define DDIM   64
#define TPB    512
#define NWARP  (TPB / 32)
#define P128   514          // ulonglong2 row pitch (512 + 2 pad): conflict-free LDS.128
#define MAXBLK 512

typedef uint32_t u32;
typedef unsigned long long u64;

__device__ double   g_partials[MAXBLK];
__device__ unsigned g_done;           // zero-init; last block resets each run

__device__ __forceinline__ u32 pack_h2(float lo, float hi) {
    // d[15:0] = f16(lo), d[31:16] = f16(hi)
    u32 r; asm("cvt.rn.f16x2.f32 %0, %1, %2;" : "=r"(r) : "f"(hi), "f"(lo));
    return r;
}
__device__ __forceinline__ float f16_residual(float v) {
    return v - __half2float(__float2half_rn(v));
}
__device__ __forceinline__ void mma_f16(float c[4], const u32 a[4], u32 b0, u32 b1) {
    asm("mma.sync.aligned.m16n8k16.row.col.f32.f16.f16.f32 "
        "{%0,%1,%2,%3}, {%4,%5,%6,%7}, {%8,%9}, {%0,%1,%2,%3};"
        : "+f"(c[0]), "+f"(c[1]), "+f"(c[2]), "+f"(c[3])
        : "r"(a[0]), "r"(a[1]), "r"(a[2]), "r"(a[3]), "r"(b0), "r"(b1));
}

__global__ void __launch_bounds__(TPB, 1)
vq_kernel(const float* __restrict__ x, const float* __restrict__ cb,
          float* __restrict__ out, int nrows)
{
    // dynamic smem: BQ[16][P128] ulonglong2 (131.6 KB) | scq[512] float
    // BQ[(4*t4+q)][c] = { u64(b0c1 | b1c1<<32), u64(b0c2 | b1c2<<32) }
    //   b0c1 = f16x2(c1[k0], c1[k0+1]), b1c1 = f16x2(c1[k0+8], c1[k0+9]), k0=16t4+2q
    extern __shared__ unsigned char smraw[];
    ulonglong2* BQ  = (ulonglong2*)smraw;
    float*      scq = (float*)(smraw + 16 * P128 * sizeof(ulonglong2));
    __shared__ int sidx[NWARP][16];

    float* out_q   = out + 1;
    float* out_idx = out + 1 + (size_t)nrows * DDIM;

    const int tid  = threadIdx.x;
    const int w    = tid >> 5;
    const int lane = tid & 31;
    const int g4   = lane >> 2;   // groupID 0..7
    const int q    = lane & 3;    // threadID-in-group 0..3

    // ---- ||c||^2 (exact fp32) ----
    for (int c = tid; c < KCODES; c += TPB) {
        const float* cr = cb + c * DDIM;
        float s = 0.f;
        #pragma unroll
        for (int i = 0; i < DDIM; i++) s = fmaf(cr[i], cr[i], s);
        scq[c] = s;
    }

    // ---- stage codebook: f16 split, fragment-packed 16B records ----
    for (int idx = tid; idx < 16 * KCODES; idx += TPB) {
        int row = idx >> 9;          // 4*t4+q, 0..15
        int c   = idx & (KCODES - 1);
        int t4  = row >> 2, qq = row & 3;
        int k0  = 16 * t4 + 2 * qq;
        const float* src = cb + (size_t)c * DDIM;
        float v0 = src[k0],     v1 = src[k0 + 1];
        float v2 = src[k0 + 8], v3 = src[k0 + 9];
        u32 b0c1 = pack_h2(v0, v1);
        u32 b1c1 = pack_h2(v2, v3);
        u32 b0c2 = pack_h2(f16_residual(v0), f16_residual(v1));
        u32 b1c2 = pack_h2(f16_residual(v2), f16_residual(v3));
        ulonglong2 val;
        val.x = (u64)b0c1 | ((u64)b1c1 << 32);
        val.y = (u64)b0c2 | ((u64)b1c2 << 32);
        BQ[(size_t)row * P128 + c] = val;
    }
    __syncthreads();

    // ---- row-group split: groups of 16 rows ----
    const int ng = nrows >> 4;                               // 8192
    const int gs = (int)(((long long)blockIdx.x * ng) / gridDim.x);
    const int ge = (int)(((long long)(blockIdx.x + 1) * ng) / gridDim.x);

    float lsum = 0.f;

    #pragma unroll 1
    for (int g = gs + w; g < ge; g += NWARP) {
        const int R = g << 4;     // 16 rows per group

        // ---- A fragments: a1 = f16(x), a2 = f16(x - f16(x)); 32 regs ----
        u32 a1[4][4], a2[4][4];
        #pragma unroll
        for (int t4 = 0; t4 < 4; t4++)
            #pragma unroll
            for (int rg = 0; rg < 4; rg++) {
                int row = R + g4 + (rg & 1) * 8;
                int col = 16 * t4 + 2 * q + (rg >> 1) * 8;
                float2 v = *(const float2*)(x + (size_t)row * DDIM + col);
                a1[t4][rg] = pack_h2(v.x, v.y);
                a2[t4][rg] = pack_h2(f16_residual(v.x), f16_residual(v.y));
            }

        const int rows0 = R + g4, rows1 = R + 8 + g4;

        float best[2] = {3.402823466e38f, 3.402823466e38f};
        int   bx[2]   = {0, 0};

        // ---- n-tiles: 8 codes each; 4 LDS.128 + 12 mma (3 indep chains) ----
        #pragma unroll 2
        for (int n = 0; n < KCODES / 8; n++) {
            float c1a[4] = {0.f, 0.f, 0.f, 0.f};   // h1 . c1
            float c2a[4] = {0.f, 0.f, 0.f, 0.f};   // h2 . c1
            float c3a[4] = {0.f, 0.f, 0.f, 0.f};   // h1 . c2
            const ulonglong2* bp = BQ + 8 * n + g4;
            #pragma unroll
            for (int t4 = 0; t4 < 4; t4++) {
                ulonglong2 v = bp[(size_t)(4 * t4 + q) * P128];
                u32 b0 = (u32)v.x, b1 = (u32)(v.x >> 32);
                u32 d0 = (u32)v.y, d1 = (u32)(v.y >> 32);
                mma_f16(c1a, a1[t4], b0, b1);
                mma_f16(c2a, a2[t4], b0, b1);
                mma_f16(c3a, a1[t4], d0, d1);
            }
            int code0 = 8 * n + 2 * q;
            float2 sq = *(const float2*)(scq + code0);
            float d;
            d = fmaf(-2.f, c1a[0] + c2a[0] + c3a[0], sq.x);
            if (d < best[0]) { best[0] = d; bx[0] = code0; }
            d = fmaf(-2.f, c1a[1] + c2a[1] + c3a[1], sq.y);
            if (d < best[0]) { best[0] = d; bx[0] = code0 + 1; }
            d = fmaf(-2.f, c1a[2] + c2a[2] + c3a[2], sq.x);
            if (d < best[1]) { best[1] = d; bx[1] = code0; }
            d = fmaf(-2.f, c1a[3] + c2a[3] + c3a[3], sq.y);
            if (d < best[1]) { best[1] = d; bx[1] = code0 + 1; }
        }

        // ---- quad reduce (lanes differing in q), first-index tie ----
        #pragma unroll
        for (int j = 0; j < 2; j++) {
            #pragma unroll
            for (int off = 1; off <= 2; off <<= 1) {
                float ob = __shfl_xor_sync(0xffffffffu, best[j], off);
                int   oi = __shfl_xor_sync(0xffffffffu, bx[j], off);
                if (ob < best[j] || (ob == best[j] && oi < bx[j])) {
                    best[j] = ob; bx[j] = oi;
                }
            }
        }

        if (q == 0) {
            out_idx[rows0] = (float)bx[0]; sidx[w][g4]     = bx[0];
            out_idx[rows1] = (float)bx[1]; sidx[w][g4 + 8] = bx[1];
        }
        __syncwarp();

        // ---- exact fp32 quantize + loss (2 dims/lane) ----
        #pragma unroll 1
        for (int r = 0; r < 16; r++) {
            int bi  = sidx[w][r];
            int row = R + r;
            float2 xv = *(const float2*)(x  + (size_t)row * DDIM + 2 * lane);
            float2 cv = *(const float2*)(cb + (size_t)bi  * DDIM + 2 * lane);
            float o0 = xv.x + (cv.x - xv.x);
            float o1 = xv.y + (cv.y - xv.y);
            float t0 = o0 - xv.x; lsum = fmaf(t0, t0, lsum);
            float t1 = o1 - xv.y; lsum = fmaf(t1, t1, lsum);
            float* oq = out_q + (size_t)row * DDIM + 2 * lane;
            oq[0] = o0;   // out_q only 4B-aligned: scalar stores
            oq[1] = o1;
        }
    }

    // ---- loss: block reduce -> double partial; last block finalizes ----
    __shared__ float warp_sums[NWARP];
    #pragma unroll
    for (int off = 16; off; off >>= 1)
        lsum += __shfl_down_sync(0xffffffffu, lsum, off);
    if (lane == 0) warp_sums[w] = lsum;
    __syncthreads();
    if (tid == 0) {
        float b = 0.f;
        #pragma unroll
        for (int i = 0; i < NWARP; i++) b += warp_sums[i];
        g_partials[blockIdx.x] = (double)b;
        __threadfence();
        unsigned done = atomicAdd(&g_done, 1u);
        if (done == gridDim.x - 1) {
            double total = 0.0;
            for (int k = 0; k < gridDim.x; k++) total += g_partials[k];
            out[0] = (float)(total * 1.25 / ((double)nrows * DDIM));
            __threadfence();
            g_done = 0;   // self-reset for graph replay
        }
    }
}

extern "C" void kernel_launch(void* const* d_in, const int* in_sizes, int n_in,
                              void* d_out, int out_size)
{
    const float* x  = (const float*)d_in[0];   // inputs  [128,32,32,64]
    const float* cb = (const float*)d_in[1];   // codebook [512,64]
    const int n_elem = in_sizes[0];            // 8388608
    const int nrows  = n_elem / DDIM;          // 131072

    const int smem_bytes = 16 * P128 * (int)sizeof(ulonglong2) + KCODES * 4;
    cudaFuncSetAttribute(vq_kernel,
                         cudaFuncAttributeMaxDynamicSharedMemorySize, smem_bytes);

    int sms = 148;
    cudaDeviceGetAttribute(&sms, cudaDevAttrMultiProcessorCount, 0);
    if (sms > MAXBLK) sms = MAXBLK;

    vq_kernel<<<sms, TPB, smem_bytes>>>(x, cb, (float*)d_out, nrows);
}